// round 2
// baseline (speedup 1.0000x reference)
#include <cuda_runtime.h>
#include <cuda_bf16.h>
#include <math.h>

#define BATCH   32
#define HIDDEN  2048
#define NH      32
#define NKV     8
#define HD      64
#define OPSZ    3072      // NH*HD + 2*NKV*HD
#define MAXBLK  128
#define KVROW   (NKV*HD)  // 512 floats per token row in cache
#define NSPLIT  4
#define SPLITLEN 512
#define CHUNK   128
#define KS      16        // k-splits for gemms

// ---------------- device scratch (no allocations allowed) ----------------
__device__ float g_qkv [BATCH*OPSZ];
__device__ float g_attn[BATCH*HIDDEN];
__device__ float g_part1[KS*BATCH*OPSZ];     // qkv gemm partials
__device__ float g_part2[KS*BATCH*HIDDEN];   // out gemm partials
__device__ float g_pm  [BATCH*NKV*NSPLIT*4];
__device__ float g_pl  [BATCH*NKV*NSPLIT*4];
__device__ float g_pout[BATCH*NKV*NSPLIT*4*HD];

// ---------------- packed f32x2 helpers (Blackwell) ----------------
__device__ __forceinline__ unsigned long long pack2(float x, float y) {
    unsigned long long r;
    asm("mov.b64 %0, {%1,%2};" : "=l"(r) : "f"(x), "f"(y));
    return r;
}
__device__ __forceinline__ void unpack2(unsigned long long v, float& x, float& y) {
    asm("mov.b64 {%0,%1}, %2;" : "=f"(x), "=f"(y) : "l"(v));
}
__device__ __forceinline__ void fma2(unsigned long long& d, unsigned long long a, unsigned long long b) {
    asm("fma.rn.f32x2 %0, %1, %2, %0;" : "+l"(d) : "l"(a), "l"(b));
}

__device__ __forceinline__ float warpMaxAll(float v) {
    #pragma unroll
    for (int o = 16; o > 0; o >>= 1) v = fmaxf(v, __shfl_xor_sync(0xffffffffu, v, o));
    return v;
}

// ---------------- GEMM: C[32,N] = A[32,K] @ W[N,K]^T, split-K partials ----------------
// grid (N/128, KS), 64 threads, tile 32x128, BK=16, thread tile 8x8 via f32x2
// WHICH=0 -> write g_part1, WHICH=1 -> write g_part2
template <int WHICH>
__global__ __launch_bounds__(64) void gemm_part_kernel(
    const float* __restrict__ A, const float* __restrict__ W, int K, int N)
{
    __shared__ __align__(16) float As[16][36];
    __shared__ __align__(16) float Ws[16][136];
    float* Cp = (WHICH == 0) ? g_part1 : g_part2;
    const int nb = blockIdx.x * 128;
    const int kchunk = K / KS;
    const int kb = blockIdx.y * kchunk;
    const int tid = threadIdx.x;
    const int ty = tid >> 4, tx = tid & 15;
    const int m0 = ty * 8, n0 = tx * 8;

    unsigned long long acc[8][4];
    #pragma unroll
    for (int i = 0; i < 8; i++)
        #pragma unroll
        for (int j = 0; j < 4; j++) acc[i][j] = 0ull;

    for (int k0 = kb; k0 < kb + kchunk; k0 += 16) {
        #pragma unroll
        for (int i = 0; i < 8; i++) {
            int idx = tid + i * 64;          // 0..511 : A tile 32x16
            As[idx & 15][idx >> 4] = A[(idx >> 4) * K + k0 + (idx & 15)];
        }
        #pragma unroll
        for (int i = 0; i < 32; i++) {
            int idx = tid + i * 64;          // 0..2047 : W tile 128x16
            Ws[idx & 15][idx >> 4] = W[(size_t)(nb + (idx >> 4)) * K + k0 + (idx & 15)];
        }
        __syncthreads();
        #pragma unroll
        for (int k = 0; k < 16; k++) {
            unsigned long long bv[4];
            const unsigned long long* wp =
                reinterpret_cast<const unsigned long long*>(&Ws[k][n0]);
            #pragma unroll
            for (int j = 0; j < 4; j++) bv[j] = wp[j];
            #pragma unroll
            for (int i = 0; i < 8; i++) {
                float a = As[k][m0 + i];
                unsigned long long av = pack2(a, a);
                #pragma unroll
                for (int j = 0; j < 4; j++) fma2(acc[i][j], av, bv[j]);
            }
        }
        __syncthreads();
    }
    #pragma unroll
    for (int i = 0; i < 8; i++) {
        float* o = Cp + (size_t)(blockIdx.y * 32 + m0 + i) * N + nb + n0;
        #pragma unroll
        for (int j = 0; j < 4; j++) {
            float x, y;
            unpack2(acc[i][j], x, y);
            o[2 * j] = x; o[2 * j + 1] = y;
        }
    }
}

// sum KS partial slices into g_qkv
__global__ void reduce_qkv_kernel()
{
    int idx = blockIdx.x * 256 + threadIdx.x;
    float s = 0.f;
    #pragma unroll
    for (int ks = 0; ks < KS; ks++) s += g_part1[(size_t)ks * 32 * OPSZ + idx];
    g_qkv[idx] = s;
}

// sum KS partial slices into d_out
__global__ void reduce_out_kernel(float* __restrict__ C)
{
    int idx = blockIdx.x * 256 + threadIdx.x;
    float s = 0.f;
    #pragma unroll
    for (int ks = 0; ks < KS; ks++) s += g_part2[(size_t)ks * 32 * HIDDEN + idx];
    C[idx] = s;
}

// ---------------- RoPE (in place on g_qkv: 32 q heads + 8 k heads) ----------------
__global__ void rope_kernel(const int* __restrict__ positions)
{
    int b = blockIdx.x;
    float pos = (float)positions[b];
    for (int idx = threadIdx.x; idx < 40 * 32; idx += blockDim.x) {
        int head = idx >> 5, i = idx & 31;
        int base = b * OPSZ + (head < NH ? head * HD : NH * HD + (head - NH) * HD);
        float inv = powf(10000.0f, -(float)i * (1.0f / 32.0f));
        float s, c;
        sincosf(pos * inv, &s, &c);
        float x1 = g_qkv[base + i], x2 = g_qkv[base + 32 + i];
        g_qkv[base + i]      = x1 * c - x2 * s;
        g_qkv[base + 32 + i] = x2 * c + x1 * s;
    }
}

// ---------------- paged attention, flash-decoding split ----------------
// grid (B, NKV, NSPLIT), 128 threads
__global__ __launch_bounds__(128) void attn_kernel(
    const float* __restrict__ kc, const float* __restrict__ vc,
    const int* __restrict__ bt, const int* __restrict__ sl)
{
    __shared__ __align__(16) float qs[4][HD];
    __shared__ __align__(16) float vs[CHUNK][HD];
    __shared__ __align__(16) float sp[CHUNK][4];
    __shared__ float s_newm[4];

    const int b = blockIdx.x, h = blockIdx.y, split = blockIdx.z;
    const int tid = threadIdx.x;
    const int w = tid >> 5, lane = tid & 31;
    const int seq = sl[b];
    const int pidx = (b * NKV + h) * NSPLIT + split;
    const int sstart = split * SPLITLEN;

    if (sstart >= seq) {
        if (tid < 4) { g_pm[pidx * 4 + tid] = -1e30f; g_pl[pidx * 4 + tid] = 0.f; }
        for (int i = tid; i < 4 * HD; i += 128) g_pout[pidx * 4 * HD + i] = 0.f;
        return;
    }
    const int send = min(seq, sstart + SPLITLEN);
    const int last = seq - 1;
    const int* btb = bt + b * MAXBLK;
    const float* qkvb = g_qkv + b * OPSZ;
    const float scale = 0.125f;  // 64^-0.5

    for (int i = tid; i < 4 * HD; i += 128)
        qs[i >> 6][i & 63] = qkvb[(h * 4 + (i >> 6)) * HD + (i & 63)] * scale;

    float acc0 = 0.f, acc1 = 0.f, run_m = -1e30f, run_l = 0.f;
    __syncthreads();

    for (int cs = sstart; cs < send; cs += CHUNK) {
        const int cend = min(send, cs + CHUNK);
        // ---- stage V chunk to smem (coalesced float4, last-token override) ----
        for (int i = tid; i < CHUNK * 16; i += 128) {
            int tl = i >> 4, d4 = i & 15;
            int t = cs + tl;
            float4 val = make_float4(0.f, 0.f, 0.f, 0.f);
            if (t < cend) {
                const float* p;
                if (t == last) {
                    p = qkvb + NH * HD + NKV * HD + h * HD;
                } else {
                    int blk = __ldg(btb + (t >> 4));
                    p = vc + ((size_t)blk * 16 + (t & 15)) * KVROW + h * HD;
                }
                val = reinterpret_cast<const float4*>(p)[d4];
            }
            reinterpret_cast<float4*>(&vs[tl][0])[d4] = val;
        }
        // ---- scores: one token per thread, 4 groups ----
        {
            int t = cs + tid;
            float s0, s1, s2, s3;
            if (t < cend) {
                const float* p;
                if (t == last) {
                    p = qkvb + NH * HD + h * HD;
                } else {
                    int blk = __ldg(btb + (t >> 4));
                    p = kc + ((size_t)blk * 16 + (t & 15)) * KVROW + h * HD;
                }
                s0 = s1 = s2 = s3 = 0.f;
                #pragma unroll
                for (int d4 = 0; d4 < 16; d4++) {
                    float4 kv = reinterpret_cast<const float4*>(p)[d4];
                    float4 q0 = reinterpret_cast<const float4*>(&qs[0][0])[d4];
                    float4 q1 = reinterpret_cast<const float4*>(&qs[1][0])[d4];
                    float4 q2 = reinterpret_cast<const float4*>(&qs[2][0])[d4];
                    float4 q3 = reinterpret_cast<const float4*>(&qs[3][0])[d4];
                    s0 += q0.x * kv.x + q0.y * kv.y + q0.z * kv.z + q0.w * kv.w;
                    s1 += q1.x * kv.x + q1.y * kv.y + q1.z * kv.z + q1.w * kv.w;
                    s2 += q2.x * kv.x + q2.y * kv.y + q2.z * kv.z + q2.w * kv.w;
                    s3 += q3.x * kv.x + q3.y * kv.y + q3.z * kv.z + q3.w * kv.w;
                }
            } else {
                s0 = s1 = s2 = s3 = -1e30f;
            }
            sp[tid][0] = s0; sp[tid][1] = s1; sp[tid][2] = s2; sp[tid][3] = s3;
        }
        __syncthreads();
        // ---- warp w owns group w: chunk max -> new running max ----
        float cm = fmaxf(fmaxf(sp[lane][w], sp[lane + 32][w]),
                         fmaxf(sp[lane + 64][w], sp[lane + 96][w]));
        cm = warpMaxAll(cm);
        float nm = fmaxf(run_m, cm);
        if (lane == 0) s_newm[w] = nm;
        __syncthreads();
        // ---- exponentiate in place ----
        {
            float4 sv = reinterpret_cast<float4*>(&sp[tid][0])[0];
            sv.x = __expf(sv.x - s_newm[0]);
            sv.y = __expf(sv.y - s_newm[1]);
            sv.z = __expf(sv.z - s_newm[2]);
            sv.w = __expf(sv.w - s_newm[3]);
            reinterpret_cast<float4*>(&sp[tid][0])[0] = sv;
        }
        __syncthreads();
        // ---- rescale accumulators + accumulate P@V (warp w: group w, lane: d pair) ----
        {
            float nm2 = s_newm[w];
            float alpha = __expf(run_m - nm2);
            run_m = nm2;
            acc0 *= alpha; acc1 *= alpha; run_l *= alpha;
            float lsum = 0.f;
            #pragma unroll 4
            for (int t = 0; t < CHUNK; t++) {
                float pv = sp[t][w];
                lsum += pv;
                float2 vv = reinterpret_cast<const float2*>(&vs[t][0])[lane];
                acc0 += pv * vv.x;
                acc1 += pv * vv.y;
            }
            run_l += lsum;
        }
        __syncthreads();
    }
    g_pout[(pidx * 4 + w) * HD + 2 * lane]     = acc0;
    g_pout[(pidx * 4 + w) * HD + 2 * lane + 1] = acc1;
    if (lane == 0) { g_pm[pidx * 4 + w] = run_m; g_pl[pidx * 4 + w] = run_l; }
}

// ---------------- combine splits via LSE ----------------
__global__ void attn_reduce_kernel()
{
    int bh = blockIdx.x;                 // b*NKV + h
    int b = bh >> 3, h = bh & 7;
    int w = threadIdx.x >> 5, lane = threadIdx.x & 31;

    float m[NSPLIT], l[NSPLIT];
    float M = -1e30f;
    #pragma unroll
    for (int s = 0; s < NSPLIT; s++) {
        m[s] = g_pm[(bh * NSPLIT + s) * 4 + w];
        l[s] = g_pl[(bh * NSPLIT + s) * 4 + w];
        M = fmaxf(M, m[s]);
    }
    float e[NSPLIT], L = 0.f;
    #pragma unroll
    for (int s = 0; s < NSPLIT; s++) { e[s] = __expf(m[s] - M); L += l[s] * e[s]; }
    float inv = 1.0f / L;
    float o0 = 0.f, o1 = 0.f;
    #pragma unroll
    for (int s = 0; s < NSPLIT; s++) {
        const float* po = g_pout + ((bh * NSPLIT + s) * 4 + w) * HD;
        o0 += po[2 * lane] * e[s];
        o1 += po[2 * lane + 1] * e[s];
    }
    float* out = g_attn + b * HIDDEN + (h * 4 + w) * HD;
    out[2 * lane]     = o0 * inv;
    out[2 * lane + 1] = o1 * inv;
}

// out-proj GEMM reads g_attn directly (A parameter = nullptr sentinel avoided
// by passing the global through a device-side alias kernel argument): simplest
// correct approach — a copy-free wrapper that forwards g_attn.
__global__ void __launch_bounds__(64) gemm_out_wrapper_dummy() {}

// ---------------- launch ----------------
extern "C" void kernel_launch(void* const* d_in, const int* in_sizes, int n_in,
                              void* d_out, int out_size)
{
    const float* hidden = (const float*)d_in[0];
    const float* wqkv   = (const float*)d_in[1];
    const float* wout   = (const float*)d_in[2];
    const float* kc     = (const float*)d_in[3];
    const float* vc     = (const float*)d_in[4];
    const int*   btab   = (const int*)d_in[5];
    const int*   slen   = (const int*)d_in[6];
    const int*   pos    = (const int*)d_in[7];
    float* out = (float*)d_out;

    static float* attn_ptr = nullptr;   // resolved once, outside capture timing-safety:
    if (attn_ptr == nullptr) {
        // cudaGetSymbolAddress is deterministic and allocation-free; doing it
        // once avoids repeating a non-stream call inside every captured replay.
        cudaGetSymbolAddress((void**)&attn_ptr, g_attn);
    }

    gemm_part_kernel<0><<<dim3(OPSZ / 128, KS), 64>>>(hidden, wqkv, HIDDEN, OPSZ);
    reduce_qkv_kernel<<<(BATCH * OPSZ) / 256, 256>>>();
    rope_kernel<<<BATCH, 256>>>(pos);
    attn_kernel<<<dim3(BATCH, NKV, NSPLIT), 128>>>(kc, vc, btab, slen);
    attn_reduce_kernel<<<BATCH * NKV, 128>>>();
    gemm_part_kernel<1><<<dim3(HIDDEN / 128, KS), 64>>>(attn_ptr, wout, HIDDEN, HIDDEN);
    reduce_out_kernel<<<(BATCH * HIDDEN) / 256, 256>>>(out);
}

// round 3
// speedup vs baseline: 1.4670x; 1.4670x over previous
#include <cuda_runtime.h>
#include <cuda_bf16.h>
#include <math.h>
#include <stdint.h>

#define BATCH   32
#define HIDDEN  2048
#define NH      32
#define NKV     8
#define HD      64
#define OPSZ    3072      // NH*HD + 2*NKV*HD
#define MAXBLK  128
#define KVROW   (NKV*HD)  // 512 floats per token row in cache
#define NSPLIT  8
#define SPLITLEN 256
#define CHUNK   128
#define KS      16        // k-splits for gemms

// ---------------- device scratch (no allocations allowed) ----------------
__device__ float g_qkv [BATCH*OPSZ];
__device__ float g_attn[BATCH*HIDDEN];
__device__ float g_part1[KS*BATCH*OPSZ];     // qkv gemm partials
__device__ float g_part2[KS*BATCH*HIDDEN];   // out gemm partials
// per-(b,h,split,warp,group) partials: index p4g = ((pidx*4+w)*4+g)
__device__ float g_pm  [BATCH*NKV*NSPLIT*16];
__device__ float g_pl  [BATCH*NKV*NSPLIT*16];
__device__ float g_pout[(size_t)BATCH*NKV*NSPLIT*16*HD];

// ---------------- packed f32x2 helpers (Blackwell) ----------------
__device__ __forceinline__ unsigned long long pack2(float x, float y) {
    unsigned long long r;
    asm("mov.b64 %0, {%1,%2};" : "=l"(r) : "f"(x), "f"(y));
    return r;
}
__device__ __forceinline__ void unpack2(unsigned long long v, float& x, float& y) {
    asm("mov.b64 {%0,%1}, %2;" : "=f"(x), "=f"(y) : "l"(v));
}
__device__ __forceinline__ void fma2(unsigned long long& d, unsigned long long a, unsigned long long b) {
    asm("fma.rn.f32x2 %0, %1, %2, %0;" : "+l"(d) : "l"(a), "l"(b));
}
__device__ __forceinline__ void cp16(uint32_t dst_smem, const void* src) {
    asm volatile("cp.async.cg.shared.global [%0], [%1], 16;" :: "r"(dst_smem), "l"(src));
}
__device__ __forceinline__ float warpMaxAll(float v) {
    #pragma unroll
    for (int o = 16; o > 0; o >>= 1) v = fmaxf(v, __shfl_xor_sync(0xffffffffu, v, o));
    return v;
}

// ---------------- GEMM: C[32,N] = A[32,K] @ W[N,K]^T, split-K partials ----------------
// grid (N/128, KS), 128 threads, tile 32x128, BK=16, thread tile 8x4 via f32x2
template <int WHICH>
__global__ __launch_bounds__(128) void gemm_part_kernel(
    const float* __restrict__ A, const float* __restrict__ W, int K, int N)
{
    __shared__ __align__(16) float As[16][36];
    __shared__ __align__(16) float Ws[16][136];
    float* Cp = (WHICH == 0) ? g_part1 : g_part2;
    const int nb = blockIdx.x * 128;
    const int kchunk = K / KS;
    const int kb = blockIdx.y * kchunk;
    const int tid = threadIdx.x;
    const int ty = tid >> 5, tx = tid & 31;
    const int m0 = ty * 8, n0 = tx * 4;

    unsigned long long acc[8][2];
    #pragma unroll
    for (int i = 0; i < 8; i++) { acc[i][0] = 0ull; acc[i][1] = 0ull; }

    for (int k0 = kb; k0 < kb + kchunk; k0 += 16) {
        #pragma unroll
        for (int i = 0; i < 4; i++) {
            int idx = tid + i * 128;          // 0..511 : A tile 32x16
            As[idx & 15][idx >> 4] = A[(idx >> 4) * K + k0 + (idx & 15)];
        }
        #pragma unroll
        for (int i = 0; i < 16; i++) {
            int idx = tid + i * 128;          // 0..2047 : W tile 128x16
            Ws[idx & 15][idx >> 4] = W[(size_t)(nb + (idx >> 4)) * K + k0 + (idx & 15)];
        }
        __syncthreads();
        #pragma unroll
        for (int k = 0; k < 16; k++) {
            float4 wv = *reinterpret_cast<const float4*>(&Ws[k][n0]);
            unsigned long long b0 = pack2(wv.x, wv.y);
            unsigned long long b1 = pack2(wv.z, wv.w);
            #pragma unroll
            for (int i = 0; i < 8; i++) {
                float a = As[k][m0 + i];
                unsigned long long av = pack2(a, a);
                fma2(acc[i][0], av, b0);
                fma2(acc[i][1], av, b1);
            }
        }
        __syncthreads();
    }
    #pragma unroll
    for (int i = 0; i < 8; i++) {
        float x0, y0, x1, y1;
        unpack2(acc[i][0], x0, y0);
        unpack2(acc[i][1], x1, y1);
        *reinterpret_cast<float4*>(
            Cp + (size_t)(blockIdx.y * 32 + m0 + i) * N + nb + n0)
            = make_float4(x0, y0, x1, y1);
    }
}

// sum KS partial slices into g_qkv
__global__ void reduce_qkv_kernel()
{
    int idx = blockIdx.x * 256 + threadIdx.x;
    float s = 0.f;
    #pragma unroll
    for (int ks = 0; ks < KS; ks++) s += g_part1[(size_t)ks * 32 * OPSZ + idx];
    g_qkv[idx] = s;
}

// sum KS partial slices into d_out
__global__ void reduce_out_kernel(float* __restrict__ C)
{
    int idx = blockIdx.x * 256 + threadIdx.x;
    float s = 0.f;
    #pragma unroll
    for (int ks = 0; ks < KS; ks++) s += g_part2[(size_t)ks * 32 * HIDDEN + idx];
    C[idx] = s;
}

// ---------------- RoPE (in place on g_qkv: 32 q heads + 8 k heads) ----------------
__global__ void rope_kernel(const int* __restrict__ positions)
{
    int b = blockIdx.x;
    float pos = (float)positions[b];
    for (int idx = threadIdx.x; idx < 40 * 32; idx += blockDim.x) {
        int head = idx >> 5, i = idx & 31;
        int base = b * OPSZ + (head < NH ? head * HD : NH * HD + (head - NH) * HD);
        float inv = powf(10000.0f, -(float)i * (1.0f / 32.0f));
        float s, c;
        sincosf(pos * inv, &s, &c);
        float x1 = g_qkv[base + i], x2 = g_qkv[base + 32 + i];
        g_qkv[base + i]      = x1 * c - x2 * s;
        g_qkv[base + 32 + i] = x2 * c + x1 * s;
    }
}

// ---------------- paged attention, flash-decoding split ----------------
// grid (B, NKV, NSPLIT), 128 threads. K and V staged coalesced via cp.async
// into one 32KB buffer (K swizzled for lane-per-token reads, V unswizzled).
// PV tokens split across warps; per-warp partials share the per-group max.
__global__ __launch_bounds__(128) void attn_kernel(
    const float* __restrict__ kc, const float* __restrict__ vc,
    const int* __restrict__ bt, const int* __restrict__ sl)
{
    __shared__ __align__(16) float qs[4][HD];
    __shared__ __align__(16) float kvbuf[CHUNK][HD];
    __shared__ __align__(16) float sp[CHUNK][4];
    __shared__ float s_run_m[4], s_alpha[4];

    const int b = blockIdx.x, h = blockIdx.y, split = blockIdx.z;
    const int tid = threadIdx.x;
    const int w = tid >> 5, lane = tid & 31;
    const int seq = sl[b];
    const int sstart = split * SPLITLEN;
    const int pidx = (b * NKV + h) * NSPLIT + split;

    if (sstart >= seq) {
        if (tid < 16) { g_pm[pidx * 16 + tid] = -1e30f; g_pl[pidx * 16 + tid] = 0.f; }
        return;
    }
    const int send = min(seq, sstart + SPLITLEN);
    const int last = seq - 1;
    const int* btb = bt + b * MAXBLK;
    const float* qkvb = g_qkv + b * OPSZ;
    const float* kL = qkvb + NH * HD + h * HD;             // fresh roped k
    const float* vL = qkvb + NH * HD + NKV * HD + h * HD;  // fresh v

    if (tid < 4) s_run_m[tid] = -1e30f;
    for (int i = tid; i < 4 * HD; i += 128)
        qs[i >> 6][i & 63] = qkvb[(h * 4 + (i >> 6)) * HD + (i & 63)] * 0.125f;

    float acc[4][2];
    float lsum[4];
    #pragma unroll
    for (int g = 0; g < 4; g++) { acc[g][0] = acc[g][1] = 0.f; lsum[g] = 0.f; }
    __syncthreads();

    for (int cs = sstart; cs < send; cs += CHUNK) {
        const int cend = min(send, cs + CHUNK);

        // ---- stage K chunk, coalesced, swizzled (cp.async) ----
        #pragma unroll
        for (int it = 0; it < 16; it++) {
            int i = tid + it * 128;
            int tl = i >> 4, d4 = i & 15;
            int t = cs + tl; if (t > last) t = last;   // clamp: data masked by -inf score
            const float* src = (t == last)
                ? (kL + d4 * 4)
                : (kc + ((size_t)__ldg(btb + (t >> 4)) * 16 + (t & 15)) * KVROW + h * HD + d4 * 4);
            int col = d4 ^ (tl & 7);
            cp16((uint32_t)__cvta_generic_to_shared(&kvbuf[tl][col * 4]), src);
        }
        asm volatile("cp.async.commit_group;\ncp.async.wait_group 0;" ::: "memory");
        __syncthreads();

        // ---- scores: thread-per-token from smem (swizzled, conflict-free) ----
        {
            int t = cs + tid;
            float4 s4 = make_float4(-1e30f, -1e30f, -1e30f, -1e30f);
            if (t < cend) {
                float s0 = 0.f, s1 = 0.f, s2 = 0.f, s3 = 0.f;
                #pragma unroll
                for (int d4 = 0; d4 < 16; d4++) {
                    int col = d4 ^ (tid & 7);
                    float4 kvv = *reinterpret_cast<const float4*>(&kvbuf[tid][col * 4]);
                    float4 q0 = *reinterpret_cast<const float4*>(&qs[0][d4 * 4]);
                    float4 q1 = *reinterpret_cast<const float4*>(&qs[1][d4 * 4]);
                    float4 q2 = *reinterpret_cast<const float4*>(&qs[2][d4 * 4]);
                    float4 q3 = *reinterpret_cast<const float4*>(&qs[3][d4 * 4]);
                    s0 += q0.x * kvv.x + q0.y * kvv.y + q0.z * kvv.z + q0.w * kvv.w;
                    s1 += q1.x * kvv.x + q1.y * kvv.y + q1.z * kvv.z + q1.w * kvv.w;
                    s2 += q2.x * kvv.x + q2.y * kvv.y + q2.z * kvv.z + q2.w * kvv.w;
                    s3 += q3.x * kvv.x + q3.y * kvv.y + q3.z * kvv.z + q3.w * kvv.w;
                }
                s4 = make_float4(s0, s1, s2, s3);
            }
            *reinterpret_cast<float4*>(&sp[tid][0]) = s4;
        }
        __syncthreads();

        // ---- issue V staging (unswizzled) — overlaps with softmax max/exp ----
        #pragma unroll
        for (int it = 0; it < 16; it++) {
            int i = tid + it * 128;
            int tl = i >> 4, d4 = i & 15;
            int t = cs + tl; if (t > last) t = last;   // garbage beyond cend: weight 0
            const float* src = (t == last)
                ? (vL + d4 * 4)
                : (vc + ((size_t)__ldg(btb + (t >> 4)) * 16 + (t & 15)) * KVROW + h * HD + d4 * 4);
            cp16((uint32_t)__cvta_generic_to_shared(&kvbuf[tl][d4 * 4]), src);
        }
        asm volatile("cp.async.commit_group;" ::: "memory");

        // ---- warp w: chunk max of group w, update running max + alpha ----
        {
            float cm = fmaxf(fmaxf(sp[lane][w], sp[lane + 32][w]),
                             fmaxf(sp[lane + 64][w], sp[lane + 96][w]));
            cm = warpMaxAll(cm);
            if (lane == 0) {
                float nm = fmaxf(s_run_m[w], cm);
                s_alpha[w] = __expf(s_run_m[w] - nm);
                s_run_m[w] = nm;
            }
        }
        __syncthreads();

        // ---- exponentiate in place ----
        {
            float4 sv = *reinterpret_cast<float4*>(&sp[tid][0]);
            sv.x = __expf(sv.x - s_run_m[0]);
            sv.y = __expf(sv.y - s_run_m[1]);
            sv.z = __expf(sv.z - s_run_m[2]);
            sv.w = __expf(sv.w - s_run_m[3]);
            *reinterpret_cast<float4*>(&sp[tid][0]) = sv;
        }
        asm volatile("cp.async.wait_group 0;" ::: "memory");
        __syncthreads();

        // ---- PV: warp w accumulates tokens [w*32, w*32+32) for all 4 groups ----
        {
            float a0 = s_alpha[0], a1 = s_alpha[1], a2 = s_alpha[2], a3 = s_alpha[3];
            acc[0][0] *= a0; acc[0][1] *= a0; lsum[0] *= a0;
            acc[1][0] *= a1; acc[1][1] *= a1; lsum[1] *= a1;
            acc[2][0] *= a2; acc[2][1] *= a2; lsum[2] *= a2;
            acc[3][0] *= a3; acc[3][1] *= a3; lsum[3] *= a3;
            #pragma unroll 8
            for (int tt = 0; tt < 32; tt++) {
                int t = w * 32 + tt;
                float4 p4 = *reinterpret_cast<const float4*>(&sp[t][0]);
                float2 vv = *reinterpret_cast<const float2*>(&kvbuf[t][lane * 2]);
                acc[0][0] += p4.x * vv.x; acc[0][1] += p4.x * vv.y; lsum[0] += p4.x;
                acc[1][0] += p4.y * vv.x; acc[1][1] += p4.y * vv.y; lsum[1] += p4.y;
                acc[2][0] += p4.z * vv.x; acc[2][1] += p4.z * vv.y; lsum[2] += p4.z;
                acc[3][0] += p4.w * vv.x; acc[3][1] += p4.w * vv.y; lsum[3] += p4.w;
            }
        }
        __syncthreads();   // protect kvbuf/sp before next chunk
    }

    // ---- emit per-warp partials (shared m per group, partial l/o) ----
    const int p = pidx * 4 + w;
    #pragma unroll
    for (int g = 0; g < 4; g++) {
        size_t o = (size_t)(p * 4 + g) * HD;
        g_pout[o + 2 * lane]     = acc[g][0];
        g_pout[o + 2 * lane + 1] = acc[g][1];
    }
    if (lane == 0) {
        #pragma unroll
        for (int g = 0; g < 4; g++) {
            g_pm[p * 4 + g] = s_run_m[g];
            g_pl[p * 4 + g] = lsum[g];
        }
    }
}

// ---------------- combine all (split, warp) partials via LSE ----------------
__global__ void attn_reduce_kernel()
{
    int bh = blockIdx.x;                 // b*NKV + h
    int b = bh >> 3, h = bh & 7;
    int g = threadIdx.x >> 5, lane = threadIdx.x & 31;
    const int S = NSPLIT * 4;

    float M = -1e30f;
    for (int s = 0; s < S; s++)
        M = fmaxf(M, g_pm[(bh * NSPLIT + (s >> 2)) * 16 + (s & 3) * 4 + g]);

    float L = 0.f, o0 = 0.f, o1 = 0.f;
    for (int s = 0; s < S; s++) {
        int idx = (bh * NSPLIT + (s >> 2)) * 16 + (s & 3) * 4 + g;
        float e = __expf(g_pm[idx] - M);
        L += g_pl[idx] * e;
        const float* po = g_pout + (size_t)idx * HD;
        o0 += po[2 * lane] * e;
        o1 += po[2 * lane + 1] * e;
    }
    float inv = 1.0f / L;
    float* out = g_attn + b * HIDDEN + (h * 4 + g) * HD;
    out[2 * lane]     = o0 * inv;
    out[2 * lane + 1] = o1 * inv;
}

// ---------------- launch ----------------
extern "C" void kernel_launch(void* const* d_in, const int* in_sizes, int n_in,
                              void* d_out, int out_size)
{
    const float* hidden = (const float*)d_in[0];
    const float* wqkv   = (const float*)d_in[1];
    const float* wout   = (const float*)d_in[2];
    const float* kc     = (const float*)d_in[3];
    const float* vc     = (const float*)d_in[4];
    const int*   btab   = (const int*)d_in[5];
    const int*   slen   = (const int*)d_in[6];
    const int*   pos    = (const int*)d_in[7];
    float* out = (float*)d_out;

    static float* attn_ptr = nullptr;
    if (attn_ptr == nullptr) {
        cudaGetSymbolAddress((void**)&attn_ptr, g_attn);
    }

    gemm_part_kernel<0><<<dim3(OPSZ / 128, KS), 128>>>(hidden, wqkv, HIDDEN, OPSZ);
    reduce_qkv_kernel<<<(BATCH * OPSZ) / 256, 256>>>();
    rope_kernel<<<BATCH, 256>>>(pos);
    attn_kernel<<<dim3(BATCH, NKV, NSPLIT), 128>>>(kc, vc, btab, slen);
    attn_reduce_kernel<<<BATCH * NKV, 128>>>();
    gemm_part_kernel<1><<<dim3(HIDDEN / 128, KS), 128>>>(attn_ptr, wout, HIDDEN, HIDDEN);
    reduce_out_kernel<<<(BATCH * HIDDEN) / 256, 256>>>(out);
}